// round 7
// baseline (speedup 1.0000x reference)
#include <cuda_runtime.h>
#include <cuda_fp16.h>
#include <cstdint>

constexpr int S_LEN = 2048;
constexpr int SEQ   = 4096;
constexpr int HID   = 2048;
constexpr int KDIM  = 2048;
constexpr float WSCALE = 64.0f;          // keep W's m-plane out of fp16 subnormals

// ---------------------------------------------------------------------------
// Scratch (__device__ globals; allocation-free rule)
// ---------------------------------------------------------------------------
__device__ __half g_osH[(size_t)S_LEN * HID];
__device__ __half g_osM[(size_t)S_LEN * HID];
__device__ __half g_wtH[(size_t)HID * HID];    // wt[k][h] = 64*W[h][k]
__device__ __half g_wtM[(size_t)HID * HID];
__device__ __half g_hiH[(size_t)SEQ * HID];
__device__ __half g_hiM[(size_t)SEQ * HID];
__device__ __half g_tH[(size_t)S_LEN * HID];   // planes of T' = 64*T
__device__ __half g_tM[(size_t)S_LEN * HID];
__device__ float g_scores[(size_t)S_LEN * SEQ];
__device__ float g_c[S_LEN];

// ---------------------------------------------------------------------------
// PTX helpers (sm_80-baseline features only: legal on .target sm_103)
// ---------------------------------------------------------------------------
__device__ __forceinline__ uint32_t smem_to_u32(const void* p) {
    uint32_t a;
    asm("{ .reg .u64 t; cvta.to.shared.u64 t, %1; cvt.u32.u64 %0, t; }" : "=r"(a) : "l"(p));
    return a;
}
__device__ __forceinline__ void cp16(uint32_t dst, const void* src) {
    asm volatile("cp.async.cg.shared.global [%0], [%1], 16;" :: "r"(dst), "l"(src));
}
__device__ __forceinline__ void cp_commit() {
    asm volatile("cp.async.commit_group;" ::: "memory");
}
template <int N>
__device__ __forceinline__ void cp_wait() {
    asm volatile("cp.async.wait_group %0;" :: "n"(N) : "memory");
}
__device__ __forceinline__ void ldm4(uint32_t* r, uint32_t addr) {
    asm volatile("ldmatrix.sync.aligned.m8n8.x4.shared.b16 {%0,%1,%2,%3}, [%4];"
                 : "=r"(r[0]), "=r"(r[1]), "=r"(r[2]), "=r"(r[3]) : "r"(addr));
}
__device__ __forceinline__ void mma16816(float* d, const uint32_t* a, const uint32_t* b) {
    asm volatile(
        "mma.sync.aligned.m16n8k16.row.col.f32.f16.f16.f32 "
        "{%0,%1,%2,%3}, {%4,%5,%6,%7}, {%8,%9}, {%0,%1,%2,%3};"
        : "+f"(d[0]), "+f"(d[1]), "+f"(d[2]), "+f"(d[3])
        : "r"(a[0]), "r"(a[1]), "r"(a[2]), "r"(a[3]), "r"(b[0]), "r"(b[1]));
}

// ---------------------------------------------------------------------------
// 2-way fp16 split helpers
// ---------------------------------------------------------------------------
__device__ __forceinline__ void split2(float a, __half& h, __half& m) {
    h = __float2half_rn(a);
    float r = a - __half2float(h);
    m = __float2half_rn(r);
}

__global__ __launch_bounds__(256) void split2_kernel(const float* __restrict__ in,
                                                     __half* __restrict__ oh,
                                                     __half* __restrict__ om,
                                                     int n4) {
    int i = blockIdx.x * 256 + threadIdx.x;
    if (i < n4) {
        float4 v = reinterpret_cast<const float4*>(in)[i];
        __half h[4], m[4];
        split2(v.x, h[0], m[0]);
        split2(v.y, h[1], m[1]);
        split2(v.z, h[2], m[2]);
        split2(v.w, h[3], m[3]);
        reinterpret_cast<__half2*>(oh)[i * 2]     = __half2{h[0], h[1]};
        reinterpret_cast<__half2*>(oh)[i * 2 + 1] = __half2{h[2], h[3]};
        reinterpret_cast<__half2*>(om)[i * 2]     = __half2{m[0], m[1]};
        reinterpret_cast<__half2*>(om)[i * 2 + 1] = __half2{m[2], m[3]};
    }
}

// W [h][k] row-major -> planes wt[k][h] = 64*W[h][k]   (transpose + scale)
__global__ __launch_bounds__(256) void splitWT_kernel(const float* __restrict__ W,
                                                      __half* __restrict__ oh,
                                                      __half* __restrict__ om) {
    __shared__ float tile[32][33];
    const int tx = threadIdx.x & 31;
    const int ty = threadIdx.x >> 5;
    const int k0 = blockIdx.x * 32;
    const int h0 = blockIdx.y * 32;
    #pragma unroll
    for (int j = 0; j < 32; j += 8)
        tile[ty + j][tx] = W[(size_t)(h0 + ty + j) * HID + k0 + tx];
    __syncthreads();
    #pragma unroll
    for (int j = 0; j < 32; j += 8) {
        float a = tile[tx][ty + j] * WSCALE;
        __half h, m;
        split2(a, h, m);
        size_t o = (size_t)(k0 + ty + j) * HID + h0 + tx;
        oh[o] = h; om[o] = m;
    }
}

// ---------------------------------------------------------------------------
// c[i] = out_state[i] . b
// ---------------------------------------------------------------------------
__global__ __launch_bounds__(256) void dot_bias_kernel(const float* __restrict__ A,
                                                       const float* __restrict__ b) {
    const int i = blockIdx.x;
    const float* row = A + (size_t)i * HID;
    float s = 0.f;
    for (int h = threadIdx.x * 4; h < HID; h += 256 * 4) {
        float4 x = *reinterpret_cast<const float4*>(row + h);
        float4 y = *reinterpret_cast<const float4*>(b + h);
        s += x.x * y.x + x.y * y.y + x.z * y.z + x.w * y.w;
    }
    __shared__ float red[8];
    #pragma unroll
    for (int o = 16; o; o >>= 1) s += __shfl_xor_sync(0xffffffffu, s, o);
    if ((threadIdx.x & 31) == 0) red[threadIdx.x >> 5] = s;
    __syncthreads();
    if (threadIdx.x == 0) {
        float t = 0.f;
        #pragma unroll
        for (int k = 0; k < 8; k++) t += red[k];
        g_c[i] = t;
    }
}

// ---------------------------------------------------------------------------
// GEMM1: CTA tile 128x256, 8 warps (2M x 4N), warp tile 64x64, 3-stage.
//   C = A @ B^T, epilogue splits C into fp16 h/m planes.
// ---------------------------------------------------------------------------
constexpr int KC      = 32;
constexpr int NC      = KDIM / KC;             // 64 chunks
constexpr int ROWB    = 80;                    // 64B data + 16B pad

constexpr int G1_NT   = 256;
constexpr int G1_RT   = 2 * (128 + G1_NT);     // 768 rows per stage
constexpr int G1_STG  = G1_RT * ROWB;          // 61440
constexpr size_t G1_SMEM = (size_t)3 * G1_STG; // 184320

__global__ __launch_bounds__(256, 1)
void gemm1_mma(const __half* __restrict__ Ah, const __half* __restrict__ Am,
               const __half* __restrict__ Bh, const __half* __restrict__ Bm,
               __half* __restrict__ Oh, __half* __restrict__ Om, int N) {
    extern __shared__ char smem[];
    const uint32_t sb = smem_to_u32(smem);
    const int tid  = threadIdx.x;
    const int lane = tid & 31;
    const int w    = tid >> 5;
    const int wm   = w & 1;
    const int wn   = w >> 1;
    const int rowBase = blockIdx.y * 128;
    const int colBase = blockIdx.x * G1_NT;

    uint32_t aOff[4], bOff[4];
    #pragma unroll
    for (int mt = 0; mt < 4; mt++)
        aOff[mt] = (uint32_t)((wm * 64 + mt * 16 + (lane & 15)) * ROWB + ((lane >> 4) << 4));
    #pragma unroll
    for (int nb = 0; nb < 4; nb++)
        bOff[nb] = (uint32_t)((wn * 64 + nb * 16 + (lane & 7) + ((lane >> 4) << 3)) * ROWB
                              + (((lane >> 3) & 1) << 4));

    float acc[4][8][4];
    #pragma unroll
    for (int mt = 0; mt < 4; mt++)
        #pragma unroll
        for (int nt = 0; nt < 8; nt++)
            #pragma unroll
            for (int q = 0; q < 4; q++) acc[mt][nt][q] = 0.f;

    const int lr = tid >> 2;
    const int lc = tid & 3;
    auto load_stage = [&](int kc) {
        const uint32_t dstStage = sb + (uint32_t)(kc % 3) * G1_STG;
        const char* srcA[2] = {(const char*)(Ah + (size_t)(rowBase + lr) * KDIM + kc * KC),
                               (const char*)(Am + (size_t)(rowBase + lr) * KDIM + kc * KC)};
        const char* srcB[2] = {(const char*)(Bh + (size_t)(colBase + lr) * KDIM + kc * KC),
                               (const char*)(Bm + (size_t)(colBase + lr) * KDIM + kc * KC)};
        #pragma unroll
        for (int p = 0; p < 2; p++) {
            #pragma unroll
            for (int j = 0; j < 2; j++) {
                const int r = lr + j * 64;
                cp16(dstStage + (uint32_t)((p * 128 + r) * ROWB + lc * 16),
                     srcA[p] + (size_t)j * 64 * KDIM * 2 + lc * 16);
            }
            #pragma unroll
            for (int j = 0; j < G1_NT / 64; j++) {
                const int r = lr + j * 64;
                cp16(dstStage + (uint32_t)((256 + p * G1_NT + r) * ROWB + lc * 16),
                     srcB[p] + (size_t)j * 64 * KDIM * 2 + lc * 16);
            }
        }
    };

    load_stage(0); cp_commit();
    load_stage(1); cp_commit();

    for (int kc = 0; kc < NC; kc++) {
        cp_wait<1>();
        __syncthreads();
        if (kc + 2 < NC) load_stage(kc + 2);
        cp_commit();

        const uint32_t base = sb + (uint32_t)(kc % 3) * G1_STG;
        #pragma unroll
        for (int s = 0; s < 2; s++) {
            uint32_t af[2][4][4];
            #pragma unroll
            for (int pa = 0; pa < 2; pa++)
                #pragma unroll
                for (int mt = 0; mt < 4; mt++)
                    ldm4(af[pa][mt], base + (uint32_t)(pa * 128 * ROWB) + aOff[mt] + s * 32);
            #pragma unroll
            for (int pb = 0; pb < 2; pb++) {
                uint32_t bf[4][4];
                #pragma unroll
                for (int nb = 0; nb < 4; nb++)
                    ldm4(bf[nb],
                         base + (uint32_t)((256 + pb * G1_NT) * ROWB) + bOff[nb] + s * 32);
                #pragma unroll
                for (int pa = 0; pa < 2; pa++) {
                    if (pa + pb > 1) continue;      // hh, hm, mh
                    #pragma unroll
                    for (int mt = 0; mt < 4; mt++)
                        #pragma unroll
                        for (int nt = 0; nt < 8; nt++)
                            mma16816(acc[mt][nt], af[pa][mt], &bf[nt >> 1][(nt & 1) * 2]);
                }
            }
        }
    }

    const int g   = lane >> 2;
    const int tig = lane & 3;
    #pragma unroll
    for (int mt = 0; mt < 4; mt++) {
        #pragma unroll
        for (int hh = 0; hh < 2; hh++) {
            const int row = rowBase + wm * 64 + mt * 16 + g + hh * 8;
            #pragma unroll
            for (int nt = 0; nt < 8; nt++) {
                const int col = colBase + wn * 64 + nt * 8 + tig * 2;
                __half h0, m0, h1, m1;
                split2(acc[mt][nt][hh * 2], h0, m0);
                split2(acc[mt][nt][hh * 2 + 1], h1, m1);
                const size_t o = (size_t)row * N + col;
                *reinterpret_cast<__half2*>(Oh + o) = __half2{h0, h1};
                *reinterpret_cast<__half2*>(Om + o) = __half2{m0, m1};
            }
        }
    }
}

// ---------------------------------------------------------------------------
// GEMM2: CTA tile 256x256, 16 warps (4M x 4N), warp tile 64x64, 2-stage.
// Grid = 16x8 = 128 CTAs -> exactly one wave on 148 SMs (no tail).
//   C_f32 = (A @ B^T)*(1/WSCALE) + bias[row]
// ---------------------------------------------------------------------------
constexpr int G2_MT   = 256;
constexpr int G2_NT   = 256;
constexpr int G2_RT   = 2 * (G2_MT + G2_NT);   // 1024 rows per stage
constexpr int G2_STG  = G2_RT * ROWB;          // 81920
constexpr size_t G2_SMEM = (size_t)2 * G2_STG; // 163840

__global__ __launch_bounds__(512, 1)
void gemm2_mma(const __half* __restrict__ Ah, const __half* __restrict__ Am,
               const __half* __restrict__ Bh, const __half* __restrict__ Bm,
               float* __restrict__ outF, const float* __restrict__ bias, int N) {
    extern __shared__ char smem[];
    const uint32_t sb = smem_to_u32(smem);
    const int tid  = threadIdx.x;
    const int lane = tid & 31;
    const int w    = tid >> 5;
    const int wm   = w & 3;        // 4 warps along M (64 rows each)
    const int wn   = w >> 2;       // 4 warps along N (64 cols each)
    const int rowBase = blockIdx.y * G2_MT;
    const int colBase = blockIdx.x * G2_NT;

    uint32_t aOff[4], bOff[4];
    #pragma unroll
    for (int mt = 0; mt < 4; mt++)
        aOff[mt] = (uint32_t)((wm * 64 + mt * 16 + (lane & 15)) * ROWB + ((lane >> 4) << 4));
    #pragma unroll
    for (int nb = 0; nb < 4; nb++)
        bOff[nb] = (uint32_t)((wn * 64 + nb * 16 + (lane & 7) + ((lane >> 4) << 3)) * ROWB
                              + (((lane >> 3) & 1) << 4));

    float acc[4][8][4];
    #pragma unroll
    for (int mt = 0; mt < 4; mt++)
        #pragma unroll
        for (int nt = 0; nt < 8; nt++)
            #pragma unroll
            for (int q = 0; q < 4; q++) acc[mt][nt][q] = 0.f;

    const int lr = tid >> 2;        // 0..127
    const int lc = tid & 3;
    auto load_stage = [&](int kc) {
        const uint32_t dstStage = sb + (uint32_t)(kc & 1) * G2_STG;
        const char* srcA[2] = {(const char*)(Ah + (size_t)(rowBase + lr) * KDIM + kc * KC),
                               (const char*)(Am + (size_t)(rowBase + lr) * KDIM + kc * KC)};
        const char* srcB[2] = {(const char*)(Bh + (size_t)(colBase + lr) * KDIM + kc * KC),
                               (const char*)(Bm + (size_t)(colBase + lr) * KDIM + kc * KC)};
        #pragma unroll
        for (int p = 0; p < 2; p++) {
            #pragma unroll
            for (int j = 0; j < G2_MT / 128; j++) {
                const int r = lr + j * 128;
                cp16(dstStage + (uint32_t)((p * G2_MT + r) * ROWB + lc * 16),
                     srcA[p] + (size_t)j * 128 * KDIM * 2 + lc * 16);
            }
            #pragma unroll
            for (int j = 0; j < G2_NT / 128; j++) {
                const int r = lr + j * 128;
                cp16(dstStage + (uint32_t)((2 * G2_MT + p * G2_NT + r) * ROWB + lc * 16),
                     srcB[p] + (size_t)j * 128 * KDIM * 2 + lc * 16);
            }
        }
    };

    load_stage(0); cp_commit();

    for (int kc = 0; kc < NC; kc++) {
        cp_wait<0>();               // stage kc resident
        __syncthreads();            // all warps done reading the other stage
        if (kc + 1 < NC) load_stage(kc + 1);
        cp_commit();                // overlaps this chunk's compute

        const uint32_t base = sb + (uint32_t)(kc & 1) * G2_STG;
        #pragma unroll
        for (int s = 0; s < 2; s++) {
            uint32_t af[2][4][4];
            #pragma unroll
            for (int pa = 0; pa < 2; pa++)
                #pragma unroll
                for (int mt = 0; mt < 4; mt++)
                    ldm4(af[pa][mt],
                         base + (uint32_t)(pa * G2_MT * ROWB) + aOff[mt] + s * 32);
            #pragma unroll
            for (int pb = 0; pb < 2; pb++) {
                uint32_t bf[4][4];
                #pragma unroll
                for (int nb = 0; nb < 4; nb++)
                    ldm4(bf[nb],
                         base + (uint32_t)((2 * G2_MT + pb * G2_NT) * ROWB) + bOff[nb]
                              + s * 32);
                #pragma unroll
                for (int pa = 0; pa < 2; pa++) {
                    if (pa + pb > 1) continue;      // hh, hm, mh
                    #pragma unroll
                    for (int mt = 0; mt < 4; mt++)
                        #pragma unroll
                        for (int nt = 0; nt < 8; nt++)
                            mma16816(acc[mt][nt], af[pa][mt], &bf[nt >> 1][(nt & 1) * 2]);
                }
            }
        }
    }

    const int g   = lane >> 2;
    const int tig = lane & 3;
    constexpr float INVS = 1.0f / WSCALE;
    #pragma unroll
    for (int mt = 0; mt < 4; mt++) {
        #pragma unroll
        for (int hh = 0; hh < 2; hh++) {
            const int row = rowBase + wm * 64 + mt * 16 + g + hh * 8;
            const float rb = bias[row];
            #pragma unroll
            for (int nt = 0; nt < 8; nt++) {
                const int col = colBase + wn * 64 + nt * 8 + tig * 2;
                *reinterpret_cast<float2*>(outF + (size_t)row * N + col) =
                    make_float2(fmaf(acc[mt][nt][hh * 2], INVS, rb),
                                fmaf(acc[mt][nt][hh * 2 + 1], INVS, rb));
            }
        }
    }
}

// ---------------------------------------------------------------------------
// Row softmax over 4096 columns
// ---------------------------------------------------------------------------
__global__ __launch_bounds__(256) void softmax_kernel(const float* __restrict__ scores,
                                                      float* __restrict__ out) {
    const int i = blockIdx.x;
    const float4* row = reinterpret_cast<const float4*>(scores + (size_t)i * SEQ);
    float4* orow = reinterpret_cast<float4*>(out + (size_t)i * SEQ);

    float4 v[4];
    float m = -1e30f;
    #pragma unroll
    for (int t = 0; t < 4; t++) {
        v[t] = row[threadIdx.x + t * 256];
        m = fmaxf(m, fmaxf(fmaxf(v[t].x, v[t].y), fmaxf(v[t].z, v[t].w)));
    }
    __shared__ float red[8];
    #pragma unroll
    for (int o = 16; o; o >>= 1) m = fmaxf(m, __shfl_xor_sync(0xffffffffu, m, o));
    if ((threadIdx.x & 31) == 0) red[threadIdx.x >> 5] = m;
    __syncthreads();
    float m_all = red[0];
    #pragma unroll
    for (int k = 1; k < 8; k++) m_all = fmaxf(m_all, red[k]);
    __syncthreads();

    float s = 0.f;
    #pragma unroll
    for (int t = 0; t < 4; t++) {
        v[t].x = __expf(v[t].x - m_all);
        v[t].y = __expf(v[t].y - m_all);
        v[t].z = __expf(v[t].z - m_all);
        v[t].w = __expf(v[t].w - m_all);
        s += v[t].x + v[t].y + v[t].z + v[t].w;
    }
    #pragma unroll
    for (int o = 16; o; o >>= 1) s += __shfl_xor_sync(0xffffffffu, s, o);
    if ((threadIdx.x & 31) == 0) red[threadIdx.x >> 5] = s;
    __syncthreads();
    float s_all = 0.f;
    #pragma unroll
    for (int k = 0; k < 8; k++) s_all += red[k];
    const float inv = 1.0f / s_all;

    #pragma unroll
    for (int t = 0; t < 4; t++) {
        float4 o4 = make_float4(v[t].x * inv, v[t].y * inv, v[t].z * inv, v[t].w * inv);
        orow[threadIdx.x + t * 256] = o4;
    }
}

// ---------------------------------------------------------------------------
extern "C" void kernel_launch(void* const* d_in, const int* in_sizes, int n_in,
                              void* d_out, int out_size) {
    const float* out_state = (const float*)d_in[0];  // [2048, 2048]
    const float* history   = (const float*)d_in[1];  // [4096, 2048]
    const float* W         = (const float*)d_in[2];  // [2048, 2048]
    const float* b         = (const float*)d_in[3];  // [2048]
    float* out = (float*)d_out;                      // [2048, 4096]

    __half *osH, *osM, *wtH, *wtM, *hiH, *hiM, *tH, *tM;
    float *scores, *cvec;
    cudaGetSymbolAddress((void**)&osH, g_osH); cudaGetSymbolAddress((void**)&osM, g_osM);
    cudaGetSymbolAddress((void**)&wtH, g_wtH); cudaGetSymbolAddress((void**)&wtM, g_wtM);
    cudaGetSymbolAddress((void**)&hiH, g_hiH); cudaGetSymbolAddress((void**)&hiM, g_hiM);
    cudaGetSymbolAddress((void**)&tH, g_tH);   cudaGetSymbolAddress((void**)&tM, g_tM);
    cudaGetSymbolAddress((void**)&scores, g_scores);
    cudaGetSymbolAddress((void**)&cvec, g_c);

    cudaFuncSetAttribute(gemm1_mma, cudaFuncAttributeMaxDynamicSharedMemorySize,
                         (int)G1_SMEM);
    cudaFuncSetAttribute(gemm2_mma, cudaFuncAttributeMaxDynamicSharedMemorySize,
                         (int)G2_SMEM);

    // 1. splits
    split2_kernel<<<(S_LEN * HID / 4 + 255) / 256, 256>>>(out_state, osH, osM,
                                                          S_LEN * HID / 4);
    split2_kernel<<<(SEQ * HID / 4 + 255) / 256, 256>>>(history, hiH, hiM,
                                                        SEQ * HID / 4);
    splitWT_kernel<<<dim3(HID / 32, HID / 32), 256>>>(W, wtH, wtM);

    // 2. c[i] = out_state[i] . b
    dot_bias_kernel<<<S_LEN, 256>>>(out_state, b);

    // 3. T' = out_state @ (64*W); epilogue splits T' into fp16 planes
    gemm1_mma<<<dim3(HID / G1_NT, S_LEN / 128), 256, G1_SMEM>>>(
        osH, osM, wtH, wtM, tH, tM, HID);

    // 4. scores = (T' @ history^T)/64 + c   — 128 CTAs, exactly one wave
    gemm2_mma<<<dim3(SEQ / G2_NT, S_LEN / G2_MT), 512, G2_SMEM>>>(
        tH, tM, hiH, hiM, scores, cvec, SEQ);

    // 5. softmax rows
    softmax_kernel<<<S_LEN, 256>>>(scores, out);
}

// round 8
// speedup vs baseline: 2.0338x; 2.0338x over previous
#include <cuda_runtime.h>
#include <cuda_fp16.h>
#include <cstdint>

constexpr int S_LEN = 2048;
constexpr int SEQ   = 4096;
constexpr int HID   = 2048;
constexpr int KDIM  = 2048;
constexpr float WSCALE = 64.0f;          // keep W's m-plane out of fp16 subnormals

// ---------------------------------------------------------------------------
// Scratch (__device__ globals; allocation-free rule)
// ---------------------------------------------------------------------------
__device__ __half g_osH[(size_t)S_LEN * HID];
__device__ __half g_osM[(size_t)S_LEN * HID];
__device__ __half g_wtH[(size_t)HID * HID];    // wt[k][h] = 64*W[h][k]
__device__ __half g_wtM[(size_t)HID * HID];
__device__ __half g_hiH[(size_t)SEQ * HID];
__device__ __half g_hiM[(size_t)SEQ * HID];
__device__ __half g_tH[(size_t)S_LEN * HID];   // planes of T' = 64*T
__device__ __half g_tM[(size_t)S_LEN * HID];
__device__ float g_scores[(size_t)S_LEN * SEQ];
__device__ float g_c[S_LEN];

// ---------------------------------------------------------------------------
// PTX helpers (sm_80-baseline features only: legal on .target sm_103)
// ---------------------------------------------------------------------------
__device__ __forceinline__ uint32_t smem_to_u32(const void* p) {
    uint32_t a;
    asm("{ .reg .u64 t; cvta.to.shared.u64 t, %1; cvt.u32.u64 %0, t; }" : "=r"(a) : "l"(p));
    return a;
}
__device__ __forceinline__ void cp16(uint32_t dst, const void* src) {
    asm volatile("cp.async.cg.shared.global [%0], [%1], 16;" :: "r"(dst), "l"(src));
}
__device__ __forceinline__ void cp_commit() {
    asm volatile("cp.async.commit_group;" ::: "memory");
}
template <int N>
__device__ __forceinline__ void cp_wait() {
    asm volatile("cp.async.wait_group %0;" :: "n"(N) : "memory");
}
__device__ __forceinline__ void ldm4(uint32_t* r, uint32_t addr) {
    asm volatile("ldmatrix.sync.aligned.m8n8.x4.shared.b16 {%0,%1,%2,%3}, [%4];"
                 : "=r"(r[0]), "=r"(r[1]), "=r"(r[2]), "=r"(r[3]) : "r"(addr));
}
__device__ __forceinline__ void mma16816(float* d, const uint32_t* a, const uint32_t* b) {
    asm volatile(
        "mma.sync.aligned.m16n8k16.row.col.f32.f16.f16.f32 "
        "{%0,%1,%2,%3}, {%4,%5,%6,%7}, {%8,%9}, {%0,%1,%2,%3};"
        : "+f"(d[0]), "+f"(d[1]), "+f"(d[2]), "+f"(d[3])
        : "r"(a[0]), "r"(a[1]), "r"(a[2]), "r"(a[3]), "r"(b[0]), "r"(b[1]));
}

// ---------------------------------------------------------------------------
// 2-way fp16 split helpers
// ---------------------------------------------------------------------------
__device__ __forceinline__ void split2(float a, __half& h, __half& m) {
    h = __float2half_rn(a);
    float r = a - __half2float(h);
    m = __float2half_rn(r);
}

__global__ __launch_bounds__(256) void split2_kernel(const float* __restrict__ in,
                                                     __half* __restrict__ oh,
                                                     __half* __restrict__ om,
                                                     int n4) {
    int i = blockIdx.x * 256 + threadIdx.x;
    if (i < n4) {
        float4 v = reinterpret_cast<const float4*>(in)[i];
        __half h[4], m[4];
        split2(v.x, h[0], m[0]);
        split2(v.y, h[1], m[1]);
        split2(v.z, h[2], m[2]);
        split2(v.w, h[3], m[3]);
        reinterpret_cast<__half2*>(oh)[i * 2]     = __half2{h[0], h[1]};
        reinterpret_cast<__half2*>(oh)[i * 2 + 1] = __half2{h[2], h[3]};
        reinterpret_cast<__half2*>(om)[i * 2]     = __half2{m[0], m[1]};
        reinterpret_cast<__half2*>(om)[i * 2 + 1] = __half2{m[2], m[3]};
    }
}

// W [h][k] row-major -> planes wt[k][h] = 64*W[h][k]   (transpose + scale)
__global__ __launch_bounds__(256) void splitWT_kernel(const float* __restrict__ W,
                                                      __half* __restrict__ oh,
                                                      __half* __restrict__ om) {
    __shared__ float tile[32][33];
    const int tx = threadIdx.x & 31;
    const int ty = threadIdx.x >> 5;
    const int k0 = blockIdx.x * 32;
    const int h0 = blockIdx.y * 32;
    #pragma unroll
    for (int j = 0; j < 32; j += 8)
        tile[ty + j][tx] = W[(size_t)(h0 + ty + j) * HID + k0 + tx];
    __syncthreads();
    #pragma unroll
    for (int j = 0; j < 32; j += 8) {
        float a = tile[tx][ty + j] * WSCALE;
        __half h, m;
        split2(a, h, m);
        size_t o = (size_t)(k0 + ty + j) * HID + h0 + tx;
        oh[o] = h; om[o] = m;
    }
}

// ---------------------------------------------------------------------------
// c[i] = out_state[i] . b
// ---------------------------------------------------------------------------
__global__ __launch_bounds__(256) void dot_bias_kernel(const float* __restrict__ A,
                                                       const float* __restrict__ b) {
    const int i = blockIdx.x;
    const float* row = A + (size_t)i * HID;
    float s = 0.f;
    for (int h = threadIdx.x * 4; h < HID; h += 256 * 4) {
        float4 x = *reinterpret_cast<const float4*>(row + h);
        float4 y = *reinterpret_cast<const float4*>(b + h);
        s += x.x * y.x + x.y * y.y + x.z * y.z + x.w * y.w;
    }
    __shared__ float red[8];
    #pragma unroll
    for (int o = 16; o; o >>= 1) s += __shfl_xor_sync(0xffffffffu, s, o);
    if ((threadIdx.x & 31) == 0) red[threadIdx.x >> 5] = s;
    __syncthreads();
    if (threadIdx.x == 0) {
        float t = 0.f;
        #pragma unroll
        for (int k = 0; k < 8; k++) t += red[k];
        g_c[i] = t;
    }
}

// ---------------------------------------------------------------------------
// GEMM1: CTA tile 128x256, 8 warps (2M x 4N), warp tile 64x64, 3-stage, occ 1.
//   C = A @ B^T, epilogue splits C into fp16 h/m planes.  (proven R6 shape)
// ---------------------------------------------------------------------------
constexpr int KC      = 32;
constexpr int NC      = KDIM / KC;             // 64 chunks
constexpr int ROWB    = 80;                    // 64B data + 16B pad

constexpr int G1_NT   = 256;
constexpr int G1_RT   = 2 * (128 + G1_NT);     // 768 rows per stage
constexpr int G1_STG  = G1_RT * ROWB;          // 61440
constexpr size_t G1_SMEM = (size_t)3 * G1_STG; // 184320

__global__ __launch_bounds__(256, 1)
void gemm1_mma(const __half* __restrict__ Ah, const __half* __restrict__ Am,
               const __half* __restrict__ Bh, const __half* __restrict__ Bm,
               __half* __restrict__ Oh, __half* __restrict__ Om, int N) {
    extern __shared__ char smem[];
    const uint32_t sb = smem_to_u32(smem);
    const int tid  = threadIdx.x;
    const int lane = tid & 31;
    const int w    = tid >> 5;
    const int wm   = w & 1;
    const int wn   = w >> 1;
    const int rowBase = blockIdx.y * 128;
    const int colBase = blockIdx.x * G1_NT;

    uint32_t aOff[4], bOff[4];
    #pragma unroll
    for (int mt = 0; mt < 4; mt++)
        aOff[mt] = (uint32_t)((wm * 64 + mt * 16 + (lane & 15)) * ROWB + ((lane >> 4) << 4));
    #pragma unroll
    for (int nb = 0; nb < 4; nb++)
        bOff[nb] = (uint32_t)((wn * 64 + nb * 16 + (lane & 7) + ((lane >> 4) << 3)) * ROWB
                              + (((lane >> 3) & 1) << 4));

    float acc[4][8][4];
    #pragma unroll
    for (int mt = 0; mt < 4; mt++)
        #pragma unroll
        for (int nt = 0; nt < 8; nt++)
            #pragma unroll
            for (int q = 0; q < 4; q++) acc[mt][nt][q] = 0.f;

    const int lr = tid >> 2;
    const int lc = tid & 3;
    auto load_stage = [&](int kc) {
        const uint32_t dstStage = sb + (uint32_t)(kc % 3) * G1_STG;
        const char* srcA[2] = {(const char*)(Ah + (size_t)(rowBase + lr) * KDIM + kc * KC),
                               (const char*)(Am + (size_t)(rowBase + lr) * KDIM + kc * KC)};
        const char* srcB[2] = {(const char*)(Bh + (size_t)(colBase + lr) * KDIM + kc * KC),
                               (const char*)(Bm + (size_t)(colBase + lr) * KDIM + kc * KC)};
        #pragma unroll
        for (int p = 0; p < 2; p++) {
            #pragma unroll
            for (int j = 0; j < 2; j++) {
                const int r = lr + j * 64;
                cp16(dstStage + (uint32_t)((p * 128 + r) * ROWB + lc * 16),
                     srcA[p] + (size_t)j * 64 * KDIM * 2 + lc * 16);
            }
            #pragma unroll
            for (int j = 0; j < G1_NT / 64; j++) {
                const int r = lr + j * 64;
                cp16(dstStage + (uint32_t)((256 + p * G1_NT + r) * ROWB + lc * 16),
                     srcB[p] + (size_t)j * 64 * KDIM * 2 + lc * 16);
            }
        }
    };

    load_stage(0); cp_commit();
    load_stage(1); cp_commit();

    for (int kc = 0; kc < NC; kc++) {
        cp_wait<1>();
        __syncthreads();
        if (kc + 2 < NC) load_stage(kc + 2);
        cp_commit();

        const uint32_t base = sb + (uint32_t)(kc % 3) * G1_STG;
        #pragma unroll
        for (int s = 0; s < 2; s++) {
            uint32_t af[2][4][4];
            #pragma unroll
            for (int pa = 0; pa < 2; pa++)
                #pragma unroll
                for (int mt = 0; mt < 4; mt++)
                    ldm4(af[pa][mt], base + (uint32_t)(pa * 128 * ROWB) + aOff[mt] + s * 32);
            #pragma unroll
            for (int pb = 0; pb < 2; pb++) {
                uint32_t bf[4][4];
                #pragma unroll
                for (int nb = 0; nb < 4; nb++)
                    ldm4(bf[nb],
                         base + (uint32_t)((256 + pb * G1_NT) * ROWB) + bOff[nb] + s * 32);
                #pragma unroll
                for (int pa = 0; pa < 2; pa++) {
                    if (pa + pb > 1) continue;      // hh, hm, mh
                    #pragma unroll
                    for (int mt = 0; mt < 4; mt++)
                        #pragma unroll
                        for (int nt = 0; nt < 8; nt++)
                            mma16816(acc[mt][nt], af[pa][mt], &bf[nt >> 1][(nt & 1) * 2]);
                }
            }
        }
    }

    const int g   = lane >> 2;
    const int tig = lane & 3;
    #pragma unroll
    for (int mt = 0; mt < 4; mt++) {
        #pragma unroll
        for (int hh = 0; hh < 2; hh++) {
            const int row = rowBase + wm * 64 + mt * 16 + g + hh * 8;
            #pragma unroll
            for (int nt = 0; nt < 8; nt++) {
                const int col = colBase + wn * 64 + nt * 8 + tig * 2;
                __half h0, m0, h1, m1;
                split2(acc[mt][nt][hh * 2], h0, m0);
                split2(acc[mt][nt][hh * 2 + 1], h1, m1);
                const size_t o = (size_t)row * N + col;
                *reinterpret_cast<__half2*>(Oh + o) = __half2{h0, h1};
                *reinterpret_cast<__half2*>(Om + o) = __half2{m0, m1};
            }
        }
    }
}

// ---------------------------------------------------------------------------
// GEMM2: CTA tile 128x128, 8 warps (2M x 4N), warp tile 64x32, 2-stage,
// __launch_bounds__(256, 2) -> 2 CTAs/SM, 4 warps/SMSP for latency hiding.
//   C_f32 = (A @ B^T)*(1/WSCALE) + bias[row]
// ---------------------------------------------------------------------------
constexpr int G2_RT   = 2 * (128 + 128);       // 512 rows per stage
constexpr int G2_STG  = G2_RT * ROWB;          // 40960
constexpr size_t G2_SMEM = (size_t)2 * G2_STG; // 81920 -> two CTAs fit (164KB<228)

__global__ __launch_bounds__(256, 2)
void gemm2_mma(const __half* __restrict__ Ah, const __half* __restrict__ Am,
               const __half* __restrict__ Bh, const __half* __restrict__ Bm,
               float* __restrict__ outF, const float* __restrict__ bias, int N) {
    extern __shared__ char smem[];
    const uint32_t sb = smem_to_u32(smem);
    const int tid  = threadIdx.x;
    const int lane = tid & 31;
    const int w    = tid >> 5;
    const int wm   = w & 1;        // 2 warps along M (64 rows each)
    const int wn   = w >> 1;       // 4 warps along N (32 cols each)
    const int rowBase = blockIdx.y * 128;
    const int colBase = blockIdx.x * 128;

    uint32_t aOff[4], bOff[2];
    #pragma unroll
    for (int mt = 0; mt < 4; mt++)
        aOff[mt] = (uint32_t)((wm * 64 + mt * 16 + (lane & 15)) * ROWB + ((lane >> 4) << 4));
    #pragma unroll
    for (int nb = 0; nb < 2; nb++)
        bOff[nb] = (uint32_t)((wn * 32 + nb * 16 + (lane & 7) + ((lane >> 4) << 3)) * ROWB
                              + (((lane >> 3) & 1) << 4));

    float acc[4][4][4];
    #pragma unroll
    for (int mt = 0; mt < 4; mt++)
        #pragma unroll
        for (int nt = 0; nt < 4; nt++)
            #pragma unroll
            for (int q = 0; q < 4; q++) acc[mt][nt][q] = 0.f;

    const int lr = tid >> 2;        // 0..63
    const int lc = tid & 3;
    auto load_stage = [&](int kc) {
        const uint32_t dstStage = sb + (uint32_t)(kc & 1) * G2_STG;
        const char* srcA[2] = {(const char*)(Ah + (size_t)(rowBase + lr) * KDIM + kc * KC),
                               (const char*)(Am + (size_t)(rowBase + lr) * KDIM + kc * KC)};
        const char* srcB[2] = {(const char*)(Bh + (size_t)(colBase + lr) * KDIM + kc * KC),
                               (const char*)(Bm + (size_t)(colBase + lr) * KDIM + kc * KC)};
        #pragma unroll
        for (int p = 0; p < 2; p++) {
            #pragma unroll
            for (int j = 0; j < 2; j++) {
                const int r = lr + j * 64;
                cp16(dstStage + (uint32_t)((p * 128 + r) * ROWB + lc * 16),
                     srcA[p] + (size_t)j * 64 * KDIM * 2 + lc * 16);
                cp16(dstStage + (uint32_t)((256 + p * 128 + r) * ROWB + lc * 16),
                     srcB[p] + (size_t)j * 64 * KDIM * 2 + lc * 16);
            }
        }
    };

    load_stage(0); cp_commit();

    for (int kc = 0; kc < NC; kc++) {
        cp_wait<0>();               // stage kc resident
        __syncthreads();            // all warps done reading the other stage
        if (kc + 1 < NC) load_stage(kc + 1);
        cp_commit();                // overlaps this chunk's compute

        const uint32_t base = sb + (uint32_t)(kc & 1) * G2_STG;
        #pragma unroll
        for (int s = 0; s < 2; s++) {
            uint32_t af[2][4][4];
            #pragma unroll
            for (int pa = 0; pa < 2; pa++)
                #pragma unroll
                for (int mt = 0; mt < 4; mt++)
                    ldm4(af[pa][mt], base + (uint32_t)(pa * 128 * ROWB) + aOff[mt] + s * 32);
            #pragma unroll
            for (int pb = 0; pb < 2; pb++) {
                uint32_t bf[2][4];
                #pragma unroll
                for (int nb = 0; nb < 2; nb++)
                    ldm4(bf[nb],
                         base + (uint32_t)((256 + pb * 128) * ROWB) + bOff[nb] + s * 32);
                #pragma unroll
                for (int pa = 0; pa < 2; pa++) {
                    if (pa + pb > 1) continue;      // hh, hm, mh
                    #pragma unroll
                    for (int mt = 0; mt < 4; mt++)
                        #pragma unroll
                        for (int nt = 0; nt < 4; nt++)
                            mma16816(acc[mt][nt], af[pa][mt], &bf[nt >> 1][(nt & 1) * 2]);
                }
            }
        }
    }

    const int g   = lane >> 2;
    const int tig = lane & 3;
    constexpr float INVS = 1.0f / WSCALE;
    #pragma unroll
    for (int mt = 0; mt < 4; mt++) {
        #pragma unroll
        for (int hh = 0; hh < 2; hh++) {
            const int row = rowBase + wm * 64 + mt * 16 + g + hh * 8;
            const float rb = bias[row];
            #pragma unroll
            for (int nt = 0; nt < 4; nt++) {
                const int col = colBase + wn * 32 + nt * 8 + tig * 2;
                *reinterpret_cast<float2*>(outF + (size_t)row * N + col) =
                    make_float2(fmaf(acc[mt][nt][hh * 2], INVS, rb),
                                fmaf(acc[mt][nt][hh * 2 + 1], INVS, rb));
            }
        }
    }
}

// ---------------------------------------------------------------------------
// Row softmax over 4096 columns
// ---------------------------------------------------------------------------
__global__ __launch_bounds__(256) void softmax_kernel(const float* __restrict__ scores,
                                                      float* __restrict__ out) {
    const int i = blockIdx.x;
    const float4* row = reinterpret_cast<const float4*>(scores + (size_t)i * SEQ);
    float4* orow = reinterpret_cast<float4*>(out + (size_t)i * SEQ);

    float4 v[4];
    float m = -1e30f;
    #pragma unroll
    for (int t = 0; t < 4; t++) {
        v[t] = row[threadIdx.x + t * 256];
        m = fmaxf(m, fmaxf(fmaxf(v[t].x, v[t].y), fmaxf(v[t].z, v[t].w)));
    }
    __shared__ float red[8];
    #pragma unroll
    for (int o = 16; o; o >>= 1) m = fmaxf(m, __shfl_xor_sync(0xffffffffu, m, o));
    if ((threadIdx.x & 31) == 0) red[threadIdx.x >> 5] = m;
    __syncthreads();
    float m_all = red[0];
    #pragma unroll
    for (int k = 1; k < 8; k++) m_all = fmaxf(m_all, red[k]);
    __syncthreads();

    float s = 0.f;
    #pragma unroll
    for (int t = 0; t < 4; t++) {
        v[t].x = __expf(v[t].x - m_all);
        v[t].y = __expf(v[t].y - m_all);
        v[t].z = __expf(v[t].z - m_all);
        v[t].w = __expf(v[t].w - m_all);
        s += v[t].x + v[t].y + v[t].z + v[t].w;
    }
    #pragma unroll
    for (int o = 16; o; o >>= 1) s += __shfl_xor_sync(0xffffffffu, s, o);
    if ((threadIdx.x & 31) == 0) red[threadIdx.x >> 5] = s;
    __syncthreads();
    float s_all = 0.f;
    #pragma unroll
    for (int k = 0; k < 8; k++) s_all += red[k];
    const float inv = 1.0f / s_all;

    #pragma unroll
    for (int t = 0; t < 4; t++) {
        float4 o4 = make_float4(v[t].x * inv, v[t].y * inv, v[t].z * inv, v[t].w * inv);
        orow[threadIdx.x + t * 256] = o4;
    }
}

// ---------------------------------------------------------------------------
extern "C" void kernel_launch(void* const* d_in, const int* in_sizes, int n_in,
                              void* d_out, int out_size) {
    const float* out_state = (const float*)d_in[0];  // [2048, 2048]
    const float* history   = (const float*)d_in[1];  // [4096, 2048]
    const float* W         = (const float*)d_in[2];  // [2048, 2048]
    const float* b         = (const float*)d_in[3];  // [2048]
    float* out = (float*)d_out;                      // [2048, 4096]

    __half *osH, *osM, *wtH, *wtM, *hiH, *hiM, *tH, *tM;
    float *scores, *cvec;
    cudaGetSymbolAddress((void**)&osH, g_osH); cudaGetSymbolAddress((void**)&osM, g_osM);
    cudaGetSymbolAddress((void**)&wtH, g_wtH); cudaGetSymbolAddress((void**)&wtM, g_wtM);
    cudaGetSymbolAddress((void**)&hiH, g_hiH); cudaGetSymbolAddress((void**)&hiM, g_hiM);
    cudaGetSymbolAddress((void**)&tH, g_tH);   cudaGetSymbolAddress((void**)&tM, g_tM);
    cudaGetSymbolAddress((void**)&scores, g_scores);
    cudaGetSymbolAddress((void**)&cvec, g_c);

    cudaFuncSetAttribute(gemm1_mma, cudaFuncAttributeMaxDynamicSharedMemorySize,
                         (int)G1_SMEM);
    cudaFuncSetAttribute(gemm2_mma, cudaFuncAttributeMaxDynamicSharedMemorySize,
                         (int)G2_SMEM);

    // 1. splits
    split2_kernel<<<(S_LEN * HID / 4 + 255) / 256, 256>>>(out_state, osH, osM,
                                                          S_LEN * HID / 4);
    split2_kernel<<<(SEQ * HID / 4 + 255) / 256, 256>>>(history, hiH, hiM,
                                                        SEQ * HID / 4);
    splitWT_kernel<<<dim3(HID / 32, HID / 32), 256>>>(W, wtH, wtM);

    // 2. c[i] = out_state[i] . b
    dot_bias_kernel<<<S_LEN, 256>>>(out_state, b);

    // 3. T' = out_state @ (64*W); epilogue splits T' into fp16 planes
    gemm1_mma<<<dim3(HID / G1_NT, S_LEN / 128), 256, G1_SMEM>>>(
        osH, osM, wtH, wtM, tH, tM, HID);

    // 4. scores = (T' @ history^T)/64 + c   — 512 CTAs @ occupancy 2
    gemm2_mma<<<dim3(SEQ / 128, S_LEN / 128), 256, G2_SMEM>>>(
        tH, tM, hiH, hiM, scores, cvec, SEQ);

    // 5. softmax rows
    softmax_kernel<<<S_LEN, 256>>>(scores, out);
}

// round 9
// speedup vs baseline: 2.1079x; 1.0364x over previous
#include <cuda_runtime.h>
#include <cuda_fp16.h>
#include <cstdint>

constexpr int S_LEN = 2048;
constexpr int SEQ   = 4096;
constexpr int HID   = 2048;
constexpr int KDIM  = 2048;
constexpr float WSCALE = 64.0f;          // keep W's m-plane out of fp16 subnormals

// ---------------------------------------------------------------------------
// Scratch (__device__ globals; allocation-free rule)
// ---------------------------------------------------------------------------
__device__ __half g_osH[(size_t)S_LEN * HID];
__device__ __half g_osM[(size_t)S_LEN * HID];
__device__ __half g_wtH[(size_t)HID * HID];    // wt[k][h] = 64*W[h][k]
__device__ __half g_wtM[(size_t)HID * HID];
__device__ __half g_hiH[(size_t)SEQ * HID];
__device__ __half g_hiM[(size_t)SEQ * HID];
__device__ __half g_tH[(size_t)S_LEN * HID];   // planes of T' = 64*T
__device__ __half g_tM[(size_t)S_LEN * HID];
__device__ float g_scores[(size_t)S_LEN * SEQ];
__device__ float g_c[S_LEN];

// ---------------------------------------------------------------------------
// PTX helpers (sm_80-baseline features only: legal on .target sm_103)
// ---------------------------------------------------------------------------
__device__ __forceinline__ uint32_t smem_to_u32(const void* p) {
    uint32_t a;
    asm("{ .reg .u64 t; cvta.to.shared.u64 t, %1; cvt.u32.u64 %0, t; }" : "=r"(a) : "l"(p));
    return a;
}
__device__ __forceinline__ void cp16(uint32_t dst, const void* src) {
    asm volatile("cp.async.cg.shared.global [%0], [%1], 16;" :: "r"(dst), "l"(src));
}
__device__ __forceinline__ void cp_commit() {
    asm volatile("cp.async.commit_group;" ::: "memory");
}
template <int N>
__device__ __forceinline__ void cp_wait() {
    asm volatile("cp.async.wait_group %0;" :: "n"(N) : "memory");
}
__device__ __forceinline__ void ldm4(uint32_t* r, uint32_t addr) {
    asm volatile("ldmatrix.sync.aligned.m8n8.x4.shared.b16 {%0,%1,%2,%3}, [%4];"
                 : "=r"(r[0]), "=r"(r[1]), "=r"(r[2]), "=r"(r[3]) : "r"(addr));
}
__device__ __forceinline__ void mma16816(float* d, const uint32_t* a, const uint32_t* b) {
    asm volatile(
        "mma.sync.aligned.m16n8k16.row.col.f32.f16.f16.f32 "
        "{%0,%1,%2,%3}, {%4,%5,%6,%7}, {%8,%9}, {%0,%1,%2,%3};"
        : "+f"(d[0]), "+f"(d[1]), "+f"(d[2]), "+f"(d[3])
        : "r"(a[0]), "r"(a[1]), "r"(a[2]), "r"(a[3]), "r"(b[0]), "r"(b[1]));
}

// ---------------------------------------------------------------------------
// 2-way fp16 split helpers
// ---------------------------------------------------------------------------
__device__ __forceinline__ void split2(float a, __half& h, __half& m) {
    h = __float2half_rn(a);
    float r = a - __half2float(h);
    m = __float2half_rn(r);
}

__global__ __launch_bounds__(256) void split2_kernel(const float* __restrict__ in,
                                                     __half* __restrict__ oh,
                                                     __half* __restrict__ om,
                                                     int n4) {
    int i = blockIdx.x * 256 + threadIdx.x;
    if (i < n4) {
        float4 v = reinterpret_cast<const float4*>(in)[i];
        __half h[4], m[4];
        split2(v.x, h[0], m[0]);
        split2(v.y, h[1], m[1]);
        split2(v.z, h[2], m[2]);
        split2(v.w, h[3], m[3]);
        reinterpret_cast<__half2*>(oh)[i * 2]     = __half2{h[0], h[1]};
        reinterpret_cast<__half2*>(oh)[i * 2 + 1] = __half2{h[2], h[3]};
        reinterpret_cast<__half2*>(om)[i * 2]     = __half2{m[0], m[1]};
        reinterpret_cast<__half2*>(om)[i * 2 + 1] = __half2{m[2], m[3]};
    }
}

// W [h][k] row-major -> planes wt[k][h] = 64*W[h][k]   (transpose + scale)
__global__ __launch_bounds__(256) void splitWT_kernel(const float* __restrict__ W,
                                                      __half* __restrict__ oh,
                                                      __half* __restrict__ om) {
    __shared__ float tile[32][33];
    const int tx = threadIdx.x & 31;
    const int ty = threadIdx.x >> 5;
    const int k0 = blockIdx.x * 32;
    const int h0 = blockIdx.y * 32;
    #pragma unroll
    for (int j = 0; j < 32; j += 8)
        tile[ty + j][tx] = W[(size_t)(h0 + ty + j) * HID + k0 + tx];
    __syncthreads();
    #pragma unroll
    for (int j = 0; j < 32; j += 8) {
        float a = tile[tx][ty + j] * WSCALE;
        __half h, m;
        split2(a, h, m);
        size_t o = (size_t)(k0 + ty + j) * HID + h0 + tx;
        oh[o] = h; om[o] = m;
    }
}

// ---------------------------------------------------------------------------
// Unified HMMA emulated-fp32 GEMM: C[M,N] = A[M,K] @ B[N,K]^T (fp16 2-way split)
// Products: hh, hm, mh.  CTA tile 128x256, 8 warps (2M x 4N), warp tile 64x64.
// KC=64, 2-stage, occ 1.
//   EPI=0: split C into fp16 h/m planes      EPI=1: C = C*(1/WSCALE) + bias[row]
//   HELP=1: blockIdx.y >= 16 are helper CTAs running split2(history) (12 CTAs)
//           and c[i]=out_state[i].b (4 CTAs) concurrently on idle SMs.
// ---------------------------------------------------------------------------
constexpr int KC    = 64;
constexpr int NCC   = KDIM / KC;               // 32 chunks
constexpr int ROWB  = 144;                     // 128B data + 16B pad
constexpr int G_NT  = 256;
constexpr int G_RT  = 2 * (128 + G_NT);        // 768 rows per stage
constexpr int G_STG = G_RT * ROWB;             // 110592
constexpr size_t G_SMEM = (size_t)2 * G_STG;   // 221184

template <int EPI, int HELP>
__global__ __launch_bounds__(256, 1)
void gemm_mma(const __half* __restrict__ Ah, const __half* __restrict__ Am,
              const __half* __restrict__ Bh, const __half* __restrict__ Bm,
              float* __restrict__ outF, __half* __restrict__ Oh,
              __half* __restrict__ Om, const float* __restrict__ bias, int N,
              const float* __restrict__ hist, __half* __restrict__ hiH,
              __half* __restrict__ hiM, const float* __restrict__ osrc,
              const float* __restrict__ bvec, float* __restrict__ cvec) {
    const int tid = threadIdx.x;

    if (HELP && blockIdx.y >= 16) {
        const int h = (blockIdx.y - 16) * 8 + blockIdx.x;   // 0..15
        if (h < 12) {
            // split2 over history, grid-strided across 12 CTAs
            const int n4 = SEQ * HID / 4;
            for (int i = h * 256 + tid; i < n4; i += 12 * 256) {
                float4 v = reinterpret_cast<const float4*>(hist)[i];
                __half hh[4], mm[4];
                split2(v.x, hh[0], mm[0]);
                split2(v.y, hh[1], mm[1]);
                split2(v.z, hh[2], mm[2]);
                split2(v.w, hh[3], mm[3]);
                reinterpret_cast<__half2*>(hiH)[i * 2]     = __half2{hh[0], hh[1]};
                reinterpret_cast<__half2*>(hiH)[i * 2 + 1] = __half2{hh[2], hh[3]};
                reinterpret_cast<__half2*>(hiM)[i * 2]     = __half2{mm[0], mm[1]};
                reinterpret_cast<__half2*>(hiM)[i * 2 + 1] = __half2{mm[2], mm[3]};
            }
        } else {
            // c[row] = out_state[row] . b ; one warp per row, 512 rows per CTA
            const int warp = tid >> 5, ln = tid & 31;
            const float4* bp = reinterpret_cast<const float4*>(bvec);
            for (int rp = 0; rp < 64; rp++) {
                const int row = (h - 12) * 512 + rp * 8 + warp;
                const float4* rowp =
                    reinterpret_cast<const float4*>(osrc + (size_t)row * HID);
                float s = 0.f;
                #pragma unroll
                for (int i = 0; i < 16; i++) {
                    float4 x = rowp[ln + i * 32];
                    float4 y = bp[ln + i * 32];
                    s += x.x * y.x + x.y * y.y + x.z * y.z + x.w * y.w;
                }
                #pragma unroll
                for (int o = 16; o; o >>= 1) s += __shfl_xor_sync(0xffffffffu, s, o);
                if (ln == 0) cvec[row] = s;
            }
        }
        return;
    }

    extern __shared__ char smem[];
    const uint32_t sb = smem_to_u32(smem);
    const int lane = tid & 31;
    const int w    = tid >> 5;
    const int wm   = w & 1;        // 2 warps along M (64 rows)
    const int wn   = w >> 1;       // 4 warps along N (64 cols)
    const int rowBase = blockIdx.y * 128;
    const int colBase = blockIdx.x * G_NT;

    uint32_t aOff[4], bOff[4];
    #pragma unroll
    for (int mt = 0; mt < 4; mt++)
        aOff[mt] = (uint32_t)((wm * 64 + mt * 16 + (lane & 15)) * ROWB + ((lane >> 4) << 4));
    #pragma unroll
    for (int nb = 0; nb < 4; nb++)
        bOff[nb] = (uint32_t)((wn * 64 + nb * 16 + (lane & 7) + ((lane >> 4) << 3)) * ROWB
                              + (((lane >> 3) & 1) << 4));

    float acc[4][8][4];
    #pragma unroll
    for (int mt = 0; mt < 4; mt++)
        #pragma unroll
        for (int nt = 0; nt < 8; nt++)
            #pragma unroll
            for (int q = 0; q < 4; q++) acc[mt][nt][q] = 0.f;

    const int lr = tid >> 2;        // 0..63
    const int lc = tid & 3;         // 16B chunk pair within 128B row
    auto load_stage = [&](int kc) {
        const uint32_t dst = sb + (uint32_t)(kc & 1) * G_STG;
        const char* sA[2] = {(const char*)(Ah + (size_t)(rowBase + lr) * KDIM + kc * KC),
                             (const char*)(Am + (size_t)(rowBase + lr) * KDIM + kc * KC)};
        const char* sB[2] = {(const char*)(Bh + (size_t)(colBase + lr) * KDIM + kc * KC),
                             (const char*)(Bm + (size_t)(colBase + lr) * KDIM + kc * KC)};
        #pragma unroll
        for (int p = 0; p < 2; p++) {
            #pragma unroll
            for (int j = 0; j < 2; j++) {          // A rows lr + 64j
                const int r = lr + j * 64;
                const char* src = sA[p] + (size_t)j * 64 * KDIM * 2;
                const uint32_t d = dst + (uint32_t)((p * 128 + r) * ROWB);
                cp16(d + lc * 16, src + lc * 16);
                cp16(d + lc * 16 + 64, src + lc * 16 + 64);
            }
            #pragma unroll
            for (int j = 0; j < 4; j++) {          // B rows lr + 64j
                const int r = lr + j * 64;
                const char* src = sB[p] + (size_t)j * 64 * KDIM * 2;
                const uint32_t d = dst + (uint32_t)((256 + p * G_NT + r) * ROWB);
                cp16(d + lc * 16, src + lc * 16);
                cp16(d + lc * 16 + 64, src + lc * 16 + 64);
            }
        }
    };

    load_stage(0); cp_commit();

    for (int kc = 0; kc < NCC; kc++) {
        cp_wait<0>();
        __syncthreads();
        if (kc + 1 < NCC) load_stage(kc + 1);
        cp_commit();

        const uint32_t base = sb + (uint32_t)(kc & 1) * G_STG;
        #pragma unroll
        for (int s = 0; s < 4; s++) {              // four k16 steps per chunk
            uint32_t af[2][4][4];
            #pragma unroll
            for (int pa = 0; pa < 2; pa++)
                #pragma unroll
                for (int mt = 0; mt < 4; mt++)
                    ldm4(af[pa][mt], base + (uint32_t)(pa * 128 * ROWB) + aOff[mt] + s * 32);
            #pragma unroll
            for (int pb = 0; pb < 2; pb++) {
                uint32_t bf[4][4];
                #pragma unroll
                for (int nb = 0; nb < 4; nb++)
                    ldm4(bf[nb],
                         base + (uint32_t)((256 + pb * G_NT) * ROWB) + bOff[nb] + s * 32);
                #pragma unroll
                for (int pa = 0; pa < 2; pa++) {
                    if (pa + pb > 1) continue;      // hh, hm, mh
                    #pragma unroll
                    for (int mt = 0; mt < 4; mt++)
                        #pragma unroll
                        for (int nt = 0; nt < 8; nt++)
                            mma16816(acc[mt][nt], af[pa][mt], &bf[nt >> 1][(nt & 1) * 2]);
                }
            }
        }
    }

    const int g   = lane >> 2;
    const int tig = lane & 3;
    constexpr float INVS = 1.0f / WSCALE;
    #pragma unroll
    for (int mt = 0; mt < 4; mt++) {
        #pragma unroll
        for (int hh = 0; hh < 2; hh++) {
            const int row = rowBase + wm * 64 + mt * 16 + g + hh * 8;
            const float rb = (EPI == 1) ? bias[row] : 0.f;
            #pragma unroll
            for (int nt = 0; nt < 8; nt++) {
                const int col = colBase + wn * 64 + nt * 8 + tig * 2;
                const float v0 = acc[mt][nt][hh * 2];
                const float v1 = acc[mt][nt][hh * 2 + 1];
                if (EPI == 0) {
                    __half h0, m0, h1, m1;
                    split2(v0, h0, m0);
                    split2(v1, h1, m1);
                    const size_t o = (size_t)row * N + col;
                    *reinterpret_cast<__half2*>(Oh + o) = __half2{h0, h1};
                    *reinterpret_cast<__half2*>(Om + o) = __half2{m0, m1};
                } else {
                    *reinterpret_cast<float2*>(outF + (size_t)row * N + col) =
                        make_float2(fmaf(v0, INVS, rb), fmaf(v1, INVS, rb));
                }
            }
        }
    }
}

// ---------------------------------------------------------------------------
// Row softmax over 4096 columns
// ---------------------------------------------------------------------------
__global__ __launch_bounds__(256) void softmax_kernel(const float* __restrict__ scores,
                                                      float* __restrict__ out) {
    const int i = blockIdx.x;
    const float4* row = reinterpret_cast<const float4*>(scores + (size_t)i * SEQ);
    float4* orow = reinterpret_cast<float4*>(out + (size_t)i * SEQ);

    float4 v[4];
    float m = -1e30f;
    #pragma unroll
    for (int t = 0; t < 4; t++) {
        v[t] = row[threadIdx.x + t * 256];
        m = fmaxf(m, fmaxf(fmaxf(v[t].x, v[t].y), fmaxf(v[t].z, v[t].w)));
    }
    __shared__ float red[8];
    #pragma unroll
    for (int o = 16; o; o >>= 1) m = fmaxf(m, __shfl_xor_sync(0xffffffffu, m, o));
    if ((threadIdx.x & 31) == 0) red[threadIdx.x >> 5] = m;
    __syncthreads();
    float m_all = red[0];
    #pragma unroll
    for (int k = 1; k < 8; k++) m_all = fmaxf(m_all, red[k]);
    __syncthreads();

    float s = 0.f;
    #pragma unroll
    for (int t = 0; t < 4; t++) {
        v[t].x = __expf(v[t].x - m_all);
        v[t].y = __expf(v[t].y - m_all);
        v[t].z = __expf(v[t].z - m_all);
        v[t].w = __expf(v[t].w - m_all);
        s += v[t].x + v[t].y + v[t].z + v[t].w;
    }
    #pragma unroll
    for (int o = 16; o; o >>= 1) s += __shfl_xor_sync(0xffffffffu, s, o);
    if ((threadIdx.x & 31) == 0) red[threadIdx.x >> 5] = s;
    __syncthreads();
    float s_all = 0.f;
    #pragma unroll
    for (int k = 0; k < 8; k++) s_all += red[k];
    const float inv = 1.0f / s_all;

    #pragma unroll
    for (int t = 0; t < 4; t++) {
        float4 o4 = make_float4(v[t].x * inv, v[t].y * inv, v[t].z * inv, v[t].w * inv);
        orow[threadIdx.x + t * 256] = o4;
    }
}

// ---------------------------------------------------------------------------
extern "C" void kernel_launch(void* const* d_in, const int* in_sizes, int n_in,
                              void* d_out, int out_size) {
    const float* out_state = (const float*)d_in[0];  // [2048, 2048]
    const float* history   = (const float*)d_in[1];  // [4096, 2048]
    const float* W         = (const float*)d_in[2];  // [2048, 2048]
    const float* b         = (const float*)d_in[3];  // [2048]
    float* out = (float*)d_out;                      // [2048, 4096]

    __half *osH, *osM, *wtH, *wtM, *hiH, *hiM, *tH, *tM;
    float *scores, *cvec;
    cudaGetSymbolAddress((void**)&osH, g_osH); cudaGetSymbolAddress((void**)&osM, g_osM);
    cudaGetSymbolAddress((void**)&wtH, g_wtH); cudaGetSymbolAddress((void**)&wtM, g_wtM);
    cudaGetSymbolAddress((void**)&hiH, g_hiH); cudaGetSymbolAddress((void**)&hiM, g_hiM);
    cudaGetSymbolAddress((void**)&tH, g_tH);   cudaGetSymbolAddress((void**)&tM, g_tM);
    cudaGetSymbolAddress((void**)&scores, g_scores);
    cudaGetSymbolAddress((void**)&cvec, g_c);

    cudaFuncSetAttribute(gemm_mma<0, 1>, cudaFuncAttributeMaxDynamicSharedMemorySize,
                         (int)G_SMEM);
    cudaFuncSetAttribute(gemm_mma<1, 0>, cudaFuncAttributeMaxDynamicSharedMemorySize,
                         (int)G_SMEM);

    // 1. prep needed BEFORE gemm1: out_state planes, W^T planes
    split2_kernel<<<(S_LEN * HID / 4 + 255) / 256, 256>>>(out_state, osH, osM,
                                                          S_LEN * HID / 4);
    splitWT_kernel<<<dim3(HID / 32, HID / 32), 256>>>(W, wtH, wtM);

    // 2. T' = out_state @ (64*W) (128 gemm CTAs) + 16 helper CTAs doing
    //    split2(history) and c[i]=out_state[i].b on otherwise-idle SMs
    gemm_mma<0, 1><<<dim3(HID / G_NT, 18), 256, G_SMEM>>>(
        osH, osM, wtH, wtM, nullptr, tH, tM, nullptr, HID,
        history, hiH, hiM, out_state, b, cvec);

    // 3. scores = (T' @ history^T)/64 + c
    gemm_mma<1, 0><<<dim3(SEQ / G_NT, S_LEN / 128), 256, G_SMEM>>>(
        tH, tM, hiH, hiM, scores, nullptr, nullptr, cvec, SEQ,
        nullptr, nullptr, nullptr, nullptr, nullptr, nullptr);

    // 4. softmax rows
    softmax_kernel<<<S_LEN, 256>>>(scores, out);
}

// round 10
// speedup vs baseline: 2.1162x; 1.0040x over previous
#include <cuda_runtime.h>
#include <cuda_fp16.h>
#include <cstdint>

constexpr int S_LEN = 2048;
constexpr int SEQ   = 4096;
constexpr int HID   = 2048;
constexpr int KDIM  = 2048;
constexpr float WSCALE = 64.0f;          // keep W's m-plane out of fp16 subnormals

// ---------------------------------------------------------------------------
// Scratch (__device__ globals; allocation-free rule)
// ---------------------------------------------------------------------------
__device__ __half g_osH[(size_t)S_LEN * HID];
__device__ __half g_osM[(size_t)S_LEN * HID];
__device__ __half g_wtH[(size_t)HID * HID];    // wt[k][h] = 64*W[h][k]
__device__ __half g_wtM[(size_t)HID * HID];
__device__ __half g_hiH[(size_t)SEQ * HID];
__device__ __half g_hiM[(size_t)SEQ * HID];
__device__ __half g_tH[(size_t)S_LEN * HID];   // planes of T' = 64*T
__device__ __half g_tM[(size_t)S_LEN * HID];
__device__ float g_scores[(size_t)S_LEN * SEQ];
__device__ float g_c[S_LEN];

// ---------------------------------------------------------------------------
// PTX helpers (sm_80-baseline features only: legal on .target sm_103)
// ---------------------------------------------------------------------------
__device__ __forceinline__ uint32_t smem_to_u32(const void* p) {
    uint32_t a;
    asm("{ .reg .u64 t; cvta.to.shared.u64 t, %1; cvt.u32.u64 %0, t; }" : "=r"(a) : "l"(p));
    return a;
}
__device__ __forceinline__ void cp16(uint32_t dst, const void* src) {
    asm volatile("cp.async.cg.shared.global [%0], [%1], 16;" :: "r"(dst), "l"(src));
}
__device__ __forceinline__ void cp_commit() {
    asm volatile("cp.async.commit_group;" ::: "memory");
}
template <int N>
__device__ __forceinline__ void cp_wait() {
    asm volatile("cp.async.wait_group %0;" :: "n"(N) : "memory");
}
__device__ __forceinline__ void ldm4(uint32_t* r, uint32_t addr) {
    asm volatile("ldmatrix.sync.aligned.m8n8.x4.shared.b16 {%0,%1,%2,%3}, [%4];"
                 : "=r"(r[0]), "=r"(r[1]), "=r"(r[2]), "=r"(r[3]) : "r"(addr));
}
__device__ __forceinline__ void mma16816(float* d, const uint32_t* a, const uint32_t* b) {
    asm volatile(
        "mma.sync.aligned.m16n8k16.row.col.f32.f16.f16.f32 "
        "{%0,%1,%2,%3}, {%4,%5,%6,%7}, {%8,%9}, {%0,%1,%2,%3};"
        : "+f"(d[0]), "+f"(d[1]), "+f"(d[2]), "+f"(d[3])
        : "r"(a[0]), "r"(a[1]), "r"(a[2]), "r"(a[3]), "r"(b[0]), "r"(b[1]));
}

// ---------------------------------------------------------------------------
// 2-way fp16 split helpers
// ---------------------------------------------------------------------------
__device__ __forceinline__ void split2(float a, __half& h, __half& m) {
    h = __float2half_rn(a);
    float r = a - __half2float(h);
    m = __float2half_rn(r);
}

__global__ __launch_bounds__(256) void split2_kernel(const float* __restrict__ in,
                                                     __half* __restrict__ oh,
                                                     __half* __restrict__ om,
                                                     int n4) {
    int i = blockIdx.x * 256 + threadIdx.x;
    if (i < n4) {
        float4 v = reinterpret_cast<const float4*>(in)[i];
        __half h[4], m[4];
        split2(v.x, h[0], m[0]);
        split2(v.y, h[1], m[1]);
        split2(v.z, h[2], m[2]);
        split2(v.w, h[3], m[3]);
        reinterpret_cast<__half2*>(oh)[i * 2]     = __half2{h[0], h[1]};
        reinterpret_cast<__half2*>(oh)[i * 2 + 1] = __half2{h[2], h[3]};
        reinterpret_cast<__half2*>(om)[i * 2]     = __half2{m[0], m[1]};
        reinterpret_cast<__half2*>(om)[i * 2 + 1] = __half2{m[2], m[3]};
    }
}

// W [h][k] row-major -> planes wt[k][h] = 64*W[h][k]   (transpose + scale)
__global__ __launch_bounds__(256) void splitWT_kernel(const float* __restrict__ W,
                                                      __half* __restrict__ oh,
                                                      __half* __restrict__ om) {
    __shared__ float tile[32][33];
    const int tx = threadIdx.x & 31;
    const int ty = threadIdx.x >> 5;
    const int k0 = blockIdx.x * 32;
    const int h0 = blockIdx.y * 32;
    #pragma unroll
    for (int j = 0; j < 32; j += 8)
        tile[ty + j][tx] = W[(size_t)(h0 + ty + j) * HID + k0 + tx];
    __syncthreads();
    #pragma unroll
    for (int j = 0; j < 32; j += 8) {
        float a = tile[tx][ty + j] * WSCALE;
        __half h, m;
        split2(a, h, m);
        size_t o = (size_t)(k0 + ty + j) * HID + h0 + tx;
        oh[o] = h; om[o] = m;
    }
}

// ---------------------------------------------------------------------------
// Unified HMMA emulated-fp32 GEMM: C[M,N] = A[M,K] @ B[N,K]^T (fp16 2-way split)
// Products: hh, hm, mh.  CTA tile 128x256, 8 warps (2M x 4N), warp tile 64x64.
// KC=64, 2-stage, occ 1.  Per k16-step: ALL 24 ldmatrix issued up front, then
// 96 MMAs in one burst -> single LDSM-latency exposure per step.
//   EPI=0: split C into fp16 h/m planes      EPI=1: C = C*(1/WSCALE) + bias[row]
//   HELP=1: blockIdx.y >= 16 are helper CTAs running split2(history) (12 CTAs)
//           and c[i]=out_state[i].b (4 CTAs) concurrently on idle SMs.
// ---------------------------------------------------------------------------
constexpr int KC    = 64;
constexpr int NCC   = KDIM / KC;               // 32 chunks
constexpr int ROWB  = 144;                     // 128B data + 16B pad
constexpr int G_NT  = 256;
constexpr int G_RT  = 2 * (128 + G_NT);        // 768 rows per stage
constexpr int G_STG = G_RT * ROWB;             // 110592
constexpr size_t G_SMEM = (size_t)2 * G_STG;   // 221184

template <int EPI, int HELP>
__global__ __launch_bounds__(256, 1)
void gemm_mma(const __half* __restrict__ Ah, const __half* __restrict__ Am,
              const __half* __restrict__ Bh, const __half* __restrict__ Bm,
              float* __restrict__ outF, __half* __restrict__ Oh,
              __half* __restrict__ Om, const float* __restrict__ bias, int N,
              const float* __restrict__ hist, __half* __restrict__ hiH,
              __half* __restrict__ hiM, const float* __restrict__ osrc,
              const float* __restrict__ bvec, float* __restrict__ cvec) {
    const int tid = threadIdx.x;

    if (HELP && blockIdx.y >= 16) {
        const int h = (blockIdx.y - 16) * 8 + blockIdx.x;   // 0..15
        if (h < 12) {
            // split2 over history, grid-strided across 12 CTAs
            const int n4 = SEQ * HID / 4;
            for (int i = h * 256 + tid; i < n4; i += 12 * 256) {
                float4 v = reinterpret_cast<const float4*>(hist)[i];
                __half hh[4], mm[4];
                split2(v.x, hh[0], mm[0]);
                split2(v.y, hh[1], mm[1]);
                split2(v.z, hh[2], mm[2]);
                split2(v.w, hh[3], mm[3]);
                reinterpret_cast<__half2*>(hiH)[i * 2]     = __half2{hh[0], hh[1]};
                reinterpret_cast<__half2*>(hiH)[i * 2 + 1] = __half2{hh[2], hh[3]};
                reinterpret_cast<__half2*>(hiM)[i * 2]     = __half2{mm[0], mm[1]};
                reinterpret_cast<__half2*>(hiM)[i * 2 + 1] = __half2{mm[2], mm[3]};
            }
        } else {
            // c[row] = out_state[row] . b ; one warp per row, 512 rows per CTA
            const int warp = tid >> 5, ln = tid & 31;
            const float4* bp = reinterpret_cast<const float4*>(bvec);
            for (int rp = 0; rp < 64; rp++) {
                const int row = (h - 12) * 512 + rp * 8 + warp;
                const float4* rowp =
                    reinterpret_cast<const float4*>(osrc + (size_t)row * HID);
                float s = 0.f;
                #pragma unroll
                for (int i = 0; i < 16; i++) {
                    float4 x = rowp[ln + i * 32];
                    float4 y = bp[ln + i * 32];
                    s += x.x * y.x + x.y * y.y + x.z * y.z + x.w * y.w;
                }
                #pragma unroll
                for (int o = 16; o; o >>= 1) s += __shfl_xor_sync(0xffffffffu, s, o);
                if (ln == 0) cvec[row] = s;
            }
        }
        return;
    }

    extern __shared__ char smem[];
    const uint32_t sb = smem_to_u32(smem);
    const int lane = tid & 31;
    const int w    = tid >> 5;
    const int wm   = w & 1;        // 2 warps along M (64 rows)
    const int wn   = w >> 1;       // 4 warps along N (64 cols)
    const int rowBase = blockIdx.y * 128;
    const int colBase = blockIdx.x * G_NT;

    uint32_t aOff[4], bOff[4];
    #pragma unroll
    for (int mt = 0; mt < 4; mt++)
        aOff[mt] = (uint32_t)((wm * 64 + mt * 16 + (lane & 15)) * ROWB + ((lane >> 4) << 4));
    #pragma unroll
    for (int nb = 0; nb < 4; nb++)
        bOff[nb] = (uint32_t)((wn * 64 + nb * 16 + (lane & 7) + ((lane >> 4) << 3)) * ROWB
                              + (((lane >> 3) & 1) << 4));

    float acc[4][8][4];
    #pragma unroll
    for (int mt = 0; mt < 4; mt++)
        #pragma unroll
        for (int nt = 0; nt < 8; nt++)
            #pragma unroll
            for (int q = 0; q < 4; q++) acc[mt][nt][q] = 0.f;

    const int lr = tid >> 2;        // 0..63
    const int lc = tid & 3;         // 16B chunk pair within 128B row
    auto load_stage = [&](int kc) {
        const uint32_t dst = sb + (uint32_t)(kc & 1) * G_STG;
        const char* sA[2] = {(const char*)(Ah + (size_t)(rowBase + lr) * KDIM + kc * KC),
                             (const char*)(Am + (size_t)(rowBase + lr) * KDIM + kc * KC)};
        const char* sB[2] = {(const char*)(Bh + (size_t)(colBase + lr) * KDIM + kc * KC),
                             (const char*)(Bm + (size_t)(colBase + lr) * KDIM + kc * KC)};
        #pragma unroll
        for (int p = 0; p < 2; p++) {
            #pragma unroll
            for (int j = 0; j < 2; j++) {          // A rows lr + 64j
                const int r = lr + j * 64;
                const char* src = sA[p] + (size_t)j * 64 * KDIM * 2;
                const uint32_t d = dst + (uint32_t)((p * 128 + r) * ROWB);
                cp16(d + lc * 16, src + lc * 16);
                cp16(d + lc * 16 + 64, src + lc * 16 + 64);
            }
            #pragma unroll
            for (int j = 0; j < 4; j++) {          // B rows lr + 64j
                const int r = lr + j * 64;
                const char* src = sB[p] + (size_t)j * 64 * KDIM * 2;
                const uint32_t d = dst + (uint32_t)((256 + p * G_NT + r) * ROWB);
                cp16(d + lc * 16, src + lc * 16);
                cp16(d + lc * 16 + 64, src + lc * 16 + 64);
            }
        }
    };

    load_stage(0); cp_commit();

    for (int kc = 0; kc < NCC; kc++) {
        cp_wait<0>();
        __syncthreads();
        if (kc + 1 < NCC) load_stage(kc + 1);
        cp_commit();

        const uint32_t base = sb + (uint32_t)(kc & 1) * G_STG;
        #pragma unroll
        for (int s = 0; s < 4; s++) {              // four k16 steps per chunk
            // ---- ALL fragment loads up front: one latency exposure ----
            uint32_t af[2][4][4];                  // 32 regs
            uint32_t bf[2][4][4];                  // 32 regs (both pb planes)
            #pragma unroll
            for (int pa = 0; pa < 2; pa++)
                #pragma unroll
                for (int mt = 0; mt < 4; mt++)
                    ldm4(af[pa][mt], base + (uint32_t)(pa * 128 * ROWB) + aOff[mt] + s * 32);
            #pragma unroll
            for (int pb = 0; pb < 2; pb++)
                #pragma unroll
                for (int nb = 0; nb < 4; nb++)
                    ldm4(bf[pb][nb],
                         base + (uint32_t)((256 + pb * G_NT) * ROWB) + bOff[nb] + s * 32);
            // ---- 96 MMAs in one burst (hh, mh, hm) ----
            #pragma unroll
            for (int pb = 0; pb < 2; pb++)
                #pragma unroll
                for (int pa = 0; pa < 2; pa++) {
                    if (pa + pb > 1) continue;      // hh, mh, hm
                    #pragma unroll
                    for (int mt = 0; mt < 4; mt++)
                        #pragma unroll
                        for (int nt = 0; nt < 8; nt++)
                            mma16816(acc[mt][nt], af[pa][mt],
                                     &bf[pb][nt >> 1][(nt & 1) * 2]);
                }
        }
    }

    const int g   = lane >> 2;
    const int tig = lane & 3;
    constexpr float INVS = 1.0f / WSCALE;
    #pragma unroll
    for (int mt = 0; mt < 4; mt++) {
        #pragma unroll
        for (int hh = 0; hh < 2; hh++) {
            const int row = rowBase + wm * 64 + mt * 16 + g + hh * 8;
            const float rb = (EPI == 1) ? bias[row] : 0.f;
            #pragma unroll
            for (int nt = 0; nt < 8; nt++) {
                const int col = colBase + wn * 64 + nt * 8 + tig * 2;
                const float v0 = acc[mt][nt][hh * 2];
                const float v1 = acc[mt][nt][hh * 2 + 1];
                if (EPI == 0) {
                    __half h0, m0, h1, m1;
                    split2(v0, h0, m0);
                    split2(v1, h1, m1);
                    const size_t o = (size_t)row * N + col;
                    *reinterpret_cast<__half2*>(Oh + o) = __half2{h0, h1};
                    *reinterpret_cast<__half2*>(Om + o) = __half2{m0, m1};
                } else {
                    *reinterpret_cast<float2*>(outF + (size_t)row * N + col) =
                        make_float2(fmaf(v0, INVS, rb), fmaf(v1, INVS, rb));
                }
            }
        }
    }
}

// ---------------------------------------------------------------------------
// Row softmax over 4096 columns
// ---------------------------------------------------------------------------
__global__ __launch_bounds__(256) void softmax_kernel(const float* __restrict__ scores,
                                                      float* __restrict__ out) {
    const int i = blockIdx.x;
    const float4* row = reinterpret_cast<const float4*>(scores + (size_t)i * SEQ);
    float4* orow = reinterpret_cast<float4*>(out + (size_t)i * SEQ);

    float4 v[4];
    float m = -1e30f;
    #pragma unroll
    for (int t = 0; t < 4; t++) {
        v[t] = row[threadIdx.x + t * 256];
        m = fmaxf(m, fmaxf(fmaxf(v[t].x, v[t].y), fmaxf(v[t].z, v[t].w)));
    }
    __shared__ float red[8];
    #pragma unroll
    for (int o = 16; o; o >>= 1) m = fmaxf(m, __shfl_xor_sync(0xffffffffu, m, o));
    if ((threadIdx.x & 31) == 0) red[threadIdx.x >> 5] = m;
    __syncthreads();
    float m_all = red[0];
    #pragma unroll
    for (int k = 1; k < 8; k++) m_all = fmaxf(m_all, red[k]);
    __syncthreads();

    float s = 0.f;
    #pragma unroll
    for (int t = 0; t < 4; t++) {
        v[t].x = __expf(v[t].x - m_all);
        v[t].y = __expf(v[t].y - m_all);
        v[t].z = __expf(v[t].z - m_all);
        v[t].w = __expf(v[t].w - m_all);
        s += v[t].x + v[t].y + v[t].z + v[t].w;
    }
    #pragma unroll
    for (int o = 16; o; o >>= 1) s += __shfl_xor_sync(0xffffffffu, s, o);
    if ((threadIdx.x & 31) == 0) red[threadIdx.x >> 5] = s;
    __syncthreads();
    float s_all = 0.f;
    #pragma unroll
    for (int k = 0; k < 8; k++) s_all += red[k];
    const float inv = 1.0f / s_all;

    #pragma unroll
    for (int t = 0; t < 4; t++) {
        float4 o4 = make_float4(v[t].x * inv, v[t].y * inv, v[t].z * inv, v[t].w * inv);
        orow[threadIdx.x + t * 256] = o4;
    }
}

// ---------------------------------------------------------------------------
extern "C" void kernel_launch(void* const* d_in, const int* in_sizes, int n_in,
                              void* d_out, int out_size) {
    const float* out_state = (const float*)d_in[0];  // [2048, 2048]
    const float* history   = (const float*)d_in[1];  // [4096, 2048]
    const float* W         = (const float*)d_in[2];  // [2048, 2048]
    const float* b         = (const float*)d_in[3];  // [2048]
    float* out = (float*)d_out;                      // [2048, 4096]

    __half *osH, *osM, *wtH, *wtM, *hiH, *hiM, *tH, *tM;
    float *scores, *cvec;
    cudaGetSymbolAddress((void**)&osH, g_osH); cudaGetSymbolAddress((void**)&osM, g_osM);
    cudaGetSymbolAddress((void**)&wtH, g_wtH); cudaGetSymbolAddress((void**)&wtM, g_wtM);
    cudaGetSymbolAddress((void**)&hiH, g_hiH); cudaGetSymbolAddress((void**)&hiM, g_hiM);
    cudaGetSymbolAddress((void**)&tH, g_tH);   cudaGetSymbolAddress((void**)&tM, g_tM);
    cudaGetSymbolAddress((void**)&scores, g_scores);
    cudaGetSymbolAddress((void**)&cvec, g_c);

    cudaFuncSetAttribute(gemm_mma<0, 1>, cudaFuncAttributeMaxDynamicSharedMemorySize,
                         (int)G_SMEM);
    cudaFuncSetAttribute(gemm_mma<1, 0>, cudaFuncAttributeMaxDynamicSharedMemorySize,
                         (int)G_SMEM);

    // 1. prep needed BEFORE gemm1: out_state planes, W^T planes
    split2_kernel<<<(S_LEN * HID / 4 + 255) / 256, 256>>>(out_state, osH, osM,
                                                          S_LEN * HID / 4);
    splitWT_kernel<<<dim3(HID / 32, HID / 32), 256>>>(W, wtH, wtM);

    // 2. T' = out_state @ (64*W) (128 gemm CTAs) + 16 helper CTAs doing
    //    split2(history) and c[i]=out_state[i].b on otherwise-idle SMs
    gemm_mma<0, 1><<<dim3(HID / G_NT, 18), 256, G_SMEM>>>(
        osH, osM, wtH, wtM, nullptr, tH, tM, nullptr, HID,
        history, hiH, hiM, out_state, b, cvec);

    // 3. scores = (T' @ history^T)/64 + c
    gemm_mma<1, 0><<<dim3(SEQ / G_NT, S_LEN / 128), 256, G_SMEM>>>(
        tH, tM, hiH, hiM, scores, nullptr, nullptr, cvec, SEQ,
        nullptr, nullptr, nullptr, nullptr, nullptr, nullptr);

    // 4. softmax rows
    softmax_kernel<<<S_LEN, 256>>>(scores, out);
}